// round 3
// baseline (speedup 1.0000x reference)
#include <cuda_runtime.h>
#include <cstdint>

// Problem constants
#define NROWS 8192
#define NCOMP 64
#define MPTS  100
#define DDIM  16
#define NCOLS (NCOMP * MPTS)          // 6400
#define NPM   ((size_t)NROWS * NCOLS) // point_resp elements

// Main-kernel tiling
#define RPB   8                        // rows per block
#define TPB   512                      // threads per block (16 warps, 2 warps per row)
#define NBLK  (NROWS / RPB)            // 1024 blocks

// Shared memory layout (floats)
#define SLOG_F   (RPB * NCOLS)         // 51200
#define SCOMP_F  (RPB * NCOMP * 2)     // 1024
#define SRED_F   (RPB * 2)             // 16
#define SMEM_F   (SLOG_F + SCOMP_F + SRED_F)
#define SMEM_BYTES (SMEM_F * 4)        // 208960 B

// -1/SIGMA * log2(e) = -10 * 1.4426950408889634
#define NEG_INV_SIGMA_LOG2E (-14.426950408889634f)

// Device scratch (static globals — no allocation)
__device__ float  d_Gf[NCOLS * DDIM];   // transformed gaussians, row-major [6400][16]
__device__ float2 d_cmeta[NCOLS];       // (g2, log2(prop_k)) per column

// ---------------- PTX helpers ----------------
__device__ __forceinline__ void ffma2(unsigned long long& d, unsigned long long a,
                                      unsigned long long b) {
    asm("fma.rn.f32x2 %0, %1, %2, %0;" : "+l"(d) : "l"(a), "l"(b));
}
__device__ __forceinline__ float2 u2f2(unsigned long long v) {
    float2 r;
    asm("mov.b64 {%0, %1}, %2;" : "=f"(r.x), "=f"(r.y) : "l"(v));
    return r;
}
__device__ __forceinline__ unsigned long long f2u2(float x, float y) {
    unsigned long long v;
    asm("mov.b64 %0, {%1, %2};" : "=l"(v) : "f"(x), "f"(y));
    return v;
}
__device__ __forceinline__ float ex2f(float x) {
    float r; asm("ex2.approx.ftz.f32 %0, %1;" : "=f"(r) : "f"(x)); return r;
}
__device__ __forceinline__ float sqrtaf(float x) {
    float r; asm("sqrt.approx.ftz.f32 %0, %1;" : "=f"(r) : "f"(x)); return r;
}

// ---------------- Kernel 1: prep (Cholesky + transform + column meta) ----------------
__global__ void gml_prep_kernel(const float* __restrict__ points,
                                const float* __restrict__ mu,
                                const float* __restrict__ cov,
                                const float* __restrict__ prop) {
    __shared__ float A[DDIM][DDIM + 1];   // cov -> chol(L) in lower triangle
    __shared__ float Gs[MPTS][DDIM];      // transformed points for this component

    const int k = blockIdx.x;
    const int tid = threadIdx.x;

    // load cov[k]
    for (int idx = tid; idx < DDIM * DDIM; idx += blockDim.x)
        A[idx >> 4][idx & 15] = cov[(size_t)k * 256 + idx];
    __syncthreads();

    // Cholesky by warp 0 (lanes = rows)
    if (tid < 32) {
        const int i = tid;
        #pragma unroll 1
        for (int j = 0; j < DDIM; ++j) {
            float diag = 0.f;
            if (i == j) { diag = sqrtf(A[j][j]); A[j][j] = diag; }
            diag = __shfl_sync(0xffffffffu, diag, j);
            if (i > j && i < DDIM) A[i][j] = A[i][j] / diag;
            __syncwarp();
            if (i > j && i < DDIM) {
                const float lij = A[i][j];
                for (int t = j + 1; t <= i; ++t) A[i][t] -= lij * A[t][j];
            }
            __syncwarp();
        }
    }
    __syncthreads();

    // G[m][e] = sum_{t<=e} points[k][m][t] * L[e][t] + mu[k][e]
    for (int idx = tid; idx < MPTS * DDIM; idx += blockDim.x) {
        const int mrow = idx >> 4, e = idx & 15;
        const float* pr = points + ((size_t)k * MPTS + mrow) * DDIM;
        float acc = mu[k * DDIM + e];
        for (int t = 0; t <= e; ++t) acc = fmaf(pr[t], A[e][t], acc);
        Gs[mrow][e] = acc;
        d_Gf[((size_t)k * MPTS + mrow) * DDIM + e] = acc;
    }
    __syncthreads();

    const float lp2 = log2f(prop[k]);
    for (int mrow = tid; mrow < MPTS; mrow += blockDim.x) {
        float s = 0.f;
        #pragma unroll
        for (int e = 0; e < DDIM; ++e) { const float v = Gs[mrow][e]; s = fmaf(v, v, s); }
        d_cmeta[k * MPTS + mrow] = make_float2(s, lp2);
    }
}

// ---------------- Kernel 2: logits + softmax + outputs ----------------
// Block: 8 rows, 16 warps (2 warps per row). Logits (log2-domain) held in smem.
// Sweep 1: compute logit2, track row max.   MUFU: 1 sqrt/pair
// Sweep 2: exp2 in place, accumulate S.     MUFU: 1 ex2/pair
// Sweep 3: scale, write point_resp, per-component sums (deterministic, no atomics).
__global__ __launch_bounds__(TPB, 1)
void gml_main_kernel(const float* __restrict__ z, float* __restrict__ out) {
    extern __shared__ float sm[];
    float* slog  = sm;                    // [RPB][NCOLS]
    float* scomp = sm + SLOG_F;           // [RPB][NCOMP][2]
    float* sred  = scomp + SCOMP_F;       // [RPB][2]

    const int tid  = threadIdx.x;
    const int lane = tid & 31;
    const int w    = tid >> 5;
    const int r    = w >> 1;              // row within block
    const int h    = w & 1;               // half (which warp of the pair)
    const int row  = (blockIdx.x << 3) + r;

    for (int i = tid; i < SCOMP_F; i += TPB) scomp[i] = 0.f;

    // load this row of z: 16 floats -> packed f32x2 regs + z2
    const float4* zf = reinterpret_cast<const float4*>(z + (size_t)row * DDIM);
    const float4 a0 = __ldg(zf + 0), a1 = __ldg(zf + 1), a2 = __ldg(zf + 2), a3 = __ldg(zf + 3);
    float z2 = a0.x * a0.x;
    z2 = fmaf(a0.y, a0.y, z2); z2 = fmaf(a0.z, a0.z, z2); z2 = fmaf(a0.w, a0.w, z2);
    z2 = fmaf(a1.x, a1.x, z2); z2 = fmaf(a1.y, a1.y, z2); z2 = fmaf(a1.z, a1.z, z2); z2 = fmaf(a1.w, a1.w, z2);
    z2 = fmaf(a2.x, a2.x, z2); z2 = fmaf(a2.y, a2.y, z2); z2 = fmaf(a2.z, a2.z, z2); z2 = fmaf(a2.w, a2.w, z2);
    z2 = fmaf(a3.x, a3.x, z2); z2 = fmaf(a3.y, a3.y, z2); z2 = fmaf(a3.z, a3.z, z2); z2 = fmaf(a3.w, a3.w, z2);
    const unsigned long long zp0 = f2u2(a0.x, a0.y), zp1 = f2u2(a0.z, a0.w);
    const unsigned long long zp2 = f2u2(a1.x, a1.y), zp3 = f2u2(a1.z, a1.w);
    const unsigned long long zp4 = f2u2(a2.x, a2.y), zp5 = f2u2(a2.z, a2.w);
    const unsigned long long zp6 = f2u2(a3.x, a3.y), zp7 = f2u2(a3.z, a3.w);

    float* srow = slog + r * NCOLS;

    // ---- Sweep 1: logits (log2 domain), running max ----
    float mrun = -3.0e38f;
    #pragma unroll 2
    for (int it = 0; it < 100; ++it) {
        const int j = it * 64 + h * 32 + lane;
        const ulonglong2* gp = reinterpret_cast<const ulonglong2*>(d_Gf + (size_t)j * DDIM);
        const ulonglong2 g0 = __ldg(gp + 0), g1 = __ldg(gp + 1);
        const ulonglong2 g2 = __ldg(gp + 2), g3 = __ldg(gp + 3);
        const float2 cm = __ldg(&d_cmeta[j]);
        unsigned long long acc0 = 0ull, acc1 = 0ull;
        ffma2(acc0, g0.x, zp0); ffma2(acc1, g0.y, zp1);
        ffma2(acc0, g1.x, zp2); ffma2(acc1, g1.y, zp3);
        ffma2(acc0, g2.x, zp4); ffma2(acc1, g2.y, zp5);
        ffma2(acc0, g3.x, zp6); ffma2(acc1, g3.y, zp7);
        const float2 s0 = u2f2(acc0), s1 = u2f2(acc1);
        const float dot = (s0.x + s0.y) + (s1.x + s1.y);
        float d2 = fmaf(dot, -2.f, z2 + cm.x);
        d2 = fmaxf(d2, 0.f);
        const float l2v = fmaf(sqrtaf(d2), NEG_INV_SIGMA_LOG2E, cm.y);
        srow[j] = l2v;
        mrun = fmaxf(mrun, l2v);
    }
    #pragma unroll
    for (int o = 16; o; o >>= 1) mrun = fmaxf(mrun, __shfl_xor_sync(0xffffffffu, mrun, o));
    if (lane == 0) sred[r * 2 + h] = mrun;
    __syncthreads();
    const float M2 = fmaxf(sred[r * 2], sred[r * 2 + 1]);
    __syncthreads();

    // ---- Sweep 2: exp2 in place, accumulate S ----
    float srun = 0.f;
    #pragma unroll 2
    for (int it = 0; it < 100; ++it) {
        const int j = it * 64 + h * 32 + lane;
        const float e = ex2f(srow[j] - M2);
        srow[j] = e;
        srun += e;
    }
    #pragma unroll
    for (int o = 16; o; o >>= 1) srun += __shfl_xor_sync(0xffffffffu, srun, o);
    if (lane == 0) sred[r * 2 + h] = srun;
    __syncthreads();
    const float invS = 1.0f / (sred[r * 2] + sred[r * 2 + 1]);

    // ---- Sweep 3: normalize, write point_resp, per-component sums ----
    // Warp pair splits each component's 100 columns: h=0 -> [0,50), h=1 -> [50,100)
    float* outp = out + (size_t)row * NCOLS;
    #pragma unroll 1
    for (int k = 0; k < NCOMP; ++k) {
        const int base = k * MPTS + h * 50;
        const float p0 = srow[base + lane] * invS;
        outp[base + lane] = p0;
        float ck = p0;
        if (lane < 18) {
            const float p1 = srow[base + 32 + lane] * invS;
            outp[base + 32 + lane] = p1;
            ck += p1;
        }
        #pragma unroll
        for (int o = 16; o; o >>= 1) ck += __shfl_xor_sync(0xffffffffu, ck, o);
        if (lane == 0) scomp[(r * NCOMP + k) * 2 + h] = ck;
    }
    __syncthreads();

    // write comp_resp: 512 values per block, one per thread
    {
        const int rr = tid >> 6, kk = tid & 63;
        const int orow = (blockIdx.x << 3) + rr;
        out[NPM + (size_t)orow * NCOMP + kk] = scomp[tid * 2] + scomp[tid * 2 + 1];
    }
}

// ---------------- launch ----------------
extern "C" void kernel_launch(void* const* d_in, const int* in_sizes, int n_in,
                              void* d_out, int out_size) {
    const float* z      = (const float*)d_in[0];
    const float* points = (const float*)d_in[1];
    const float* mu     = (const float*)d_in[2];
    const float* cov    = (const float*)d_in[3];
    const float* prop   = (const float*)d_in[4];
    float* out = (float*)d_out;

    cudaFuncSetAttribute(gml_main_kernel, cudaFuncAttributeMaxDynamicSharedMemorySize,
                         SMEM_BYTES);

    gml_prep_kernel<<<NCOMP, 128>>>(points, mu, cov, prop);
    gml_main_kernel<<<NBLK, TPB, SMEM_BYTES>>>(z, out);
}

// round 8
// speedup vs baseline: 2.7835x; 2.7835x over previous
#include <cuda_runtime.h>
#include <cstdint>

// Problem constants
#define NROWS 8192
#define NCOMP 64
#define MPTS  100
#define DDIM  16
#define NCOLS (NCOMP * MPTS)          // 6400
#define NPM   ((size_t)NROWS * NCOLS) // point_resp elements

// Main-kernel tiling
#define RPB   8                        // rows per block
#define TPB   512                      // threads per block (16 warps)
#define NBLK  (NROWS / RPB)            // 1024 blocks
#define NSTRIPE 8                      // column stripes (warps per row-half)
#define COLS_PER_STRIPE (NCOLS / NSTRIPE)   // 800
#define ITERS_S1 (COLS_PER_STRIPE / 32)     // 25

// Shared memory layout (floats)
#define SLOG_F   (RPB * NCOLS)         // 51200
#define SCOMP_F  (RPB * NCOMP * 2)     // 1024
#define SREDA_F  (RPB * NSTRIPE)       // 64  (per-row per-stripe maxes)
#define SREDB_F  (RPB * 2)             // 16  (per-row sum partials)
#define SMEM_F   (SLOG_F + SCOMP_F + SREDA_F + SREDB_F)
#define SMEM_BYTES (SMEM_F * 4)        // 209216 B

// -1/SIGMA * log2(e) = -10 * 1.4426950408889634
#define NEG_INV_SIGMA_LOG2E (-14.426950408889634f)

// Device scratch (static globals — no allocation)
// Transposed-packed gaussians: d_Gt4[e4 * NCOLS + col] holds dims [4e4..4e4+3] of column col.
__device__ float4 d_Gt4[4 * NCOLS];
__device__ float2 d_cmeta[NCOLS];       // (g2, log2(prop_k)) per column

// ---------------- PTX helpers ----------------
__device__ __forceinline__ void ffma2(unsigned long long& d, unsigned long long a,
                                      unsigned long long b) {
    asm("fma.rn.f32x2 %0, %1, %2, %0;" : "+l"(d) : "l"(a), "l"(b));
}
__device__ __forceinline__ float2 u2f2(unsigned long long v) {
    float2 r;
    asm("mov.b64 {%0, %1}, %2;" : "=f"(r.x), "=f"(r.y) : "l"(v));
    return r;
}
__device__ __forceinline__ unsigned long long f2u2(float x, float y) {
    unsigned long long v;
    asm("mov.b64 %0, {%1, %2};" : "=l"(v) : "f"(x), "f"(y));
    return v;
}
__device__ __forceinline__ float ex2f(float x) {
    float r; asm("ex2.approx.ftz.f32 %0, %1;" : "=f"(r) : "f"(x)); return r;
}
__device__ __forceinline__ float sqrtaf(float x) {
    float r; asm("sqrt.approx.ftz.f32 %0, %1;" : "=f"(r) : "f"(x)); return r;
}

// ---------------- Kernel 1: prep (Cholesky + transform + column meta) ----------------
__global__ void gml_prep_kernel(const float* __restrict__ points,
                                const float* __restrict__ mu,
                                const float* __restrict__ cov,
                                const float* __restrict__ prop) {
    __shared__ float A[DDIM][DDIM + 1];   // cov -> chol(L) in lower triangle
    __shared__ float Gs[MPTS][DDIM];      // transformed points for this component

    const int k = blockIdx.x;
    const int tid = threadIdx.x;

    // load cov[k]
    for (int idx = tid; idx < DDIM * DDIM; idx += blockDim.x)
        A[idx >> 4][idx & 15] = cov[(size_t)k * 256 + idx];
    __syncthreads();

    // Cholesky by warp 0 (lanes = rows)
    if (tid < 32) {
        const int i = tid;
        #pragma unroll 1
        for (int j = 0; j < DDIM; ++j) {
            float diag = 0.f;
            if (i == j) { diag = sqrtf(A[j][j]); A[j][j] = diag; }
            diag = __shfl_sync(0xffffffffu, diag, j);
            if (i > j && i < DDIM) A[i][j] = A[i][j] / diag;
            __syncwarp();
            if (i > j && i < DDIM) {
                const float lij = A[i][j];
                for (int t = j + 1; t <= i; ++t) A[i][t] -= lij * A[t][j];
            }
            __syncwarp();
        }
    }
    __syncthreads();

    // G[m][e] = sum_{t<=e} points[k][m][t] * L[e][t] + mu[k][e]
    for (int idx = tid; idx < MPTS * DDIM; idx += blockDim.x) {
        const int mrow = idx >> 4, e = idx & 15;
        const float* pr = points + ((size_t)k * MPTS + mrow) * DDIM;
        float acc = mu[k * DDIM + e];
        for (int t = 0; t <= e; ++t) acc = fmaf(pr[t], A[e][t], acc);
        Gs[mrow][e] = acc;
    }
    __syncthreads();

    // write transposed-packed Gt4 + cmeta
    for (int idx = tid; idx < MPTS * 4; idx += blockDim.x) {
        const int mrow = idx >> 2, e4 = idx & 3;
        const int col = k * MPTS + mrow;
        d_Gt4[e4 * NCOLS + col] = make_float4(Gs[mrow][4 * e4 + 0], Gs[mrow][4 * e4 + 1],
                                              Gs[mrow][4 * e4 + 2], Gs[mrow][4 * e4 + 3]);
    }

    const float lp2 = log2f(prop[k]);
    for (int mrow = tid; mrow < MPTS; mrow += blockDim.x) {
        float s = 0.f;
        #pragma unroll
        for (int e = 0; e < DDIM; ++e) { const float v = Gs[mrow][e]; s = fmaf(v, v, s); }
        d_cmeta[k * MPTS + mrow] = make_float2(s, lp2);
    }
}

// ---------------- Kernel 2: logits + softmax + outputs ----------------
// Sweep 1: warp w handles rows [rh*4, rh*4+4) (rh = w&1) x column stripe (w>>1) of 800 cols.
//          G column loads coalesced (transposed layout), amortized over 4 rows.
// Sweep 2/3: warp-pair-per-row mapping (as R3), logits resident in smem.
__global__ __launch_bounds__(TPB, 1)
void gml_main_kernel(const float* __restrict__ z, float* __restrict__ out) {
    extern __shared__ float sm[];
    float* slog  = sm;                    // [RPB][NCOLS]
    float* scomp = sm + SLOG_F;           // [RPB][NCOMP][2]
    float* sredA = scomp + SCOMP_F;       // [RPB][NSTRIPE]
    float* sredB = sredA + SREDA_F;       // [RPB][2]

    const int tid  = threadIdx.x;
    const int lane = tid & 31;
    const int w    = tid >> 5;

    // ---- Sweep-1 mapping ----
    const int rh      = w & 1;            // row half: rows rh*4 .. rh*4+3
    const int cstripe = w >> 1;           // column stripe 0..7
    const int jbase   = cstripe * COLS_PER_STRIPE;
    const int row0    = (blockIdx.x << 3) + rh * 4;

    // load z for 4 rows -> packed f32x2 regs + z2
    unsigned long long zp[4][8];
    float z2[4];
    #pragma unroll
    for (int r = 0; r < 4; ++r) {
        const float4* zf = reinterpret_cast<const float4*>(z + (size_t)(row0 + r) * DDIM);
        const float4 a0 = __ldg(zf + 0), a1 = __ldg(zf + 1);
        const float4 a2 = __ldg(zf + 2), a3 = __ldg(zf + 3);
        float s = a0.x * a0.x;
        s = fmaf(a0.y, a0.y, s); s = fmaf(a0.z, a0.z, s); s = fmaf(a0.w, a0.w, s);
        s = fmaf(a1.x, a1.x, s); s = fmaf(a1.y, a1.y, s); s = fmaf(a1.z, a1.z, s); s = fmaf(a1.w, a1.w, s);
        s = fmaf(a2.x, a2.x, s); s = fmaf(a2.y, a2.y, s); s = fmaf(a2.z, a2.z, s); s = fmaf(a2.w, a2.w, s);
        s = fmaf(a3.x, a3.x, s); s = fmaf(a3.y, a3.y, s); s = fmaf(a3.z, a3.z, s); s = fmaf(a3.w, a3.w, s);
        z2[r] = s;
        zp[r][0] = f2u2(a0.x, a0.y); zp[r][1] = f2u2(a0.z, a0.w);
        zp[r][2] = f2u2(a1.x, a1.y); zp[r][3] = f2u2(a1.z, a1.w);
        zp[r][4] = f2u2(a2.x, a2.y); zp[r][5] = f2u2(a2.z, a2.w);
        zp[r][6] = f2u2(a3.x, a3.y); zp[r][7] = f2u2(a3.z, a3.w);
    }

    const ulonglong2* gt = reinterpret_cast<const ulonglong2*>(d_Gt4);
    float* slog_h = slog + (rh * 4) * NCOLS;

    // ---- Sweep 1: logits (log2 domain), running max per row ----
    float mrun[4] = {-3.0e38f, -3.0e38f, -3.0e38f, -3.0e38f};
    #pragma unroll 1
    for (int it = 0; it < ITERS_S1; ++it) {
        const int j = jbase + it * 32 + lane;
        const ulonglong2 ga = __ldg(gt + 0 * NCOLS + j);
        const ulonglong2 gb = __ldg(gt + 1 * NCOLS + j);
        const ulonglong2 gc = __ldg(gt + 2 * NCOLS + j);
        const ulonglong2 gd = __ldg(gt + 3 * NCOLS + j);
        const float2 cm = __ldg(&d_cmeta[j]);
        #pragma unroll
        for (int r = 0; r < 4; ++r) {
            unsigned long long acc0 = 0ull, acc1 = 0ull;
            ffma2(acc0, ga.x, zp[r][0]); ffma2(acc1, ga.y, zp[r][1]);
            ffma2(acc0, gb.x, zp[r][2]); ffma2(acc1, gb.y, zp[r][3]);
            ffma2(acc0, gc.x, zp[r][4]); ffma2(acc1, gc.y, zp[r][5]);
            ffma2(acc0, gd.x, zp[r][6]); ffma2(acc1, gd.y, zp[r][7]);
            const float2 s0 = u2f2(acc0), s1 = u2f2(acc1);
            const float dot = (s0.x + s0.y) + (s1.x + s1.y);
            float d2 = fmaf(dot, -2.f, z2[r] + cm.x);
            d2 = fmaxf(d2, 0.f);
            const float l2v = fmaf(sqrtaf(d2), NEG_INV_SIGMA_LOG2E, cm.y);
            slog_h[r * NCOLS + j] = l2v;
            mrun[r] = fmaxf(mrun[r], l2v);
        }
    }
    #pragma unroll
    for (int r = 0; r < 4; ++r) {
        float m = mrun[r];
        #pragma unroll
        for (int o = 16; o; o >>= 1) m = fmaxf(m, __shfl_xor_sync(0xffffffffu, m, o));
        if (lane == 0) sredA[(rh * 4 + r) * NSTRIPE + cstripe] = m;
    }
    __syncthreads();

    // ---- Sweep-2/3 mapping: warp pair per row ----
    const int r    = w >> 1;              // row within block
    const int h    = w & 1;               // which warp of the pair
    const int row  = (blockIdx.x << 3) + r;
    float* srow = slog + r * NCOLS;

    float M2 = sredA[r * NSTRIPE];
    #pragma unroll
    for (int s = 1; s < NSTRIPE; ++s) M2 = fmaxf(M2, sredA[r * NSTRIPE + s]);

    // ---- Sweep 2: exp2 in place, accumulate S ----
    float srun = 0.f;
    #pragma unroll 2
    for (int it = 0; it < 100; ++it) {
        const int j = it * 64 + h * 32 + lane;
        const float e = ex2f(srow[j] - M2);
        srow[j] = e;
        srun += e;
    }
    #pragma unroll
    for (int o = 16; o; o >>= 1) srun += __shfl_xor_sync(0xffffffffu, srun, o);
    if (lane == 0) sredB[r * 2 + h] = srun;
    __syncthreads();
    const float invS = 1.0f / (sredB[r * 2] + sredB[r * 2 + 1]);

    // ---- Sweep 3: normalize, write point_resp, per-component sums ----
    float* outp = out + (size_t)row * NCOLS;
    #pragma unroll 1
    for (int k = 0; k < NCOMP; ++k) {
        const int base = k * MPTS + h * 50;
        const float p0 = srow[base + lane] * invS;
        outp[base + lane] = p0;
        float ck = p0;
        if (lane < 18) {
            const float p1 = srow[base + 32 + lane] * invS;
            outp[base + 32 + lane] = p1;
            ck += p1;
        }
        #pragma unroll
        for (int o = 16; o; o >>= 1) ck += __shfl_xor_sync(0xffffffffu, ck, o);
        if (lane == 0) scomp[(r * NCOMP + k) * 2 + h] = ck;
    }
    __syncthreads();

    // write comp_resp: 512 values per block, one per thread
    {
        const int rr = tid >> 6, kk = tid & 63;
        const int orow = (blockIdx.x << 3) + rr;
        out[NPM + (size_t)orow * NCOMP + kk] = scomp[tid * 2] + scomp[tid * 2 + 1];
    }
}

// ---------------- launch ----------------
extern "C" void kernel_launch(void* const* d_in, const int* in_sizes, int n_in,
                              void* d_out, int out_size) {
    const float* z      = (const float*)d_in[0];
    const float* points = (const float*)d_in[1];
    const float* mu     = (const float*)d_in[2];
    const float* cov    = (const float*)d_in[3];
    const float* prop   = (const float*)d_in[4];
    float* out = (float*)d_out;

    cudaFuncSetAttribute(gml_main_kernel, cudaFuncAttributeMaxDynamicSharedMemorySize,
                         SMEM_BYTES);

    gml_prep_kernel<<<NCOMP, 128>>>(points, mu, cov, prop);
    gml_main_kernel<<<NBLK, TPB, SMEM_BYTES>>>(z, out);
}

// round 15
// speedup vs baseline: 2.9144x; 1.0470x over previous
#include <cuda_runtime.h>
#include <cstdint>

// Problem constants
#define NROWS 8192
#define NCOMP 64
#define MPTS  100
#define DDIM  16
#define NCOLS (NCOMP * MPTS)          // 6400
#define NPM   ((size_t)NROWS * NCOLS) // point_resp elements

// Main-kernel tiling: 4 rows/block, 256 threads (8 warps), 2 CTAs/SM
#define RPB   4
#define TPB   256
#define NBLK  (NROWS / RPB)            // 2048 blocks
#define NSTRIPE 8                      // column stripes (one per warp in sweep 1)
#define COLS_PER_STRIPE (NCOLS / NSTRIPE)   // 800
#define ITERS_S1 (COLS_PER_STRIPE / 32)     // 25

// Shared memory layout (floats)
#define SLOG_F   (RPB * NCOLS)         // 25600
#define SCOMP_F  (RPB * NCOMP * 2)     // 512
#define SREDA_F  (RPB * NSTRIPE)       // 32  (per-row per-stripe maxes)
#define SREDB_F  (RPB * 2)             // 8   (per-row sum partials)
#define SMEM_F   (SLOG_F + SCOMP_F + SREDA_F + SREDB_F)
#define SMEM_BYTES (SMEM_F * 4)        // 104608 B -> 2 CTAs/SM

// -1/SIGMA * log2(e) = -10 * 1.4426950408889634
#define NEG_INV_SIGMA_LOG2E (-14.426950408889634f)

// Device scratch (static globals — no allocation)
// Transposed-packed gaussians: d_Gt4[e4 * NCOLS + col] holds dims [4e4..4e4+3] of column col.
__device__ float4 d_Gt4[4 * NCOLS];
__device__ float2 d_cmeta[NCOLS];       // (g2, log2(prop_k)) per column

// ---------------- PTX helpers ----------------
__device__ __forceinline__ void ffma2(unsigned long long& d, unsigned long long a,
                                      unsigned long long b) {
    asm("fma.rn.f32x2 %0, %1, %2, %0;" : "+l"(d) : "l"(a), "l"(b));
}
__device__ __forceinline__ float2 u2f2(unsigned long long v) {
    float2 r;
    asm("mov.b64 {%0, %1}, %2;" : "=f"(r.x), "=f"(r.y) : "l"(v));
    return r;
}
__device__ __forceinline__ unsigned long long f2u2(float x, float y) {
    unsigned long long v;
    asm("mov.b64 %0, {%1, %2};" : "=l"(v) : "f"(x), "f"(y));
    return v;
}
__device__ __forceinline__ float ex2f(float x) {
    float r; asm("ex2.approx.ftz.f32 %0, %1;" : "=f"(r) : "f"(x)); return r;
}
__device__ __forceinline__ float sqrtaf(float x) {
    float r; asm("sqrt.approx.ftz.f32 %0, %1;" : "=f"(r) : "f"(x)); return r;
}

// ---------------- Kernel 1: prep (Cholesky + transform + column meta) ----------------
__global__ void gml_prep_kernel(const float* __restrict__ points,
                                const float* __restrict__ mu,
                                const float* __restrict__ cov,
                                const float* __restrict__ prop) {
    __shared__ float A[DDIM][DDIM + 1];   // cov -> chol(L) in lower triangle
    __shared__ float Gs[MPTS][DDIM];      // transformed points for this component

    const int k = blockIdx.x;
    const int tid = threadIdx.x;

    // load cov[k]
    for (int idx = tid; idx < DDIM * DDIM; idx += blockDim.x)
        A[idx >> 4][idx & 15] = cov[(size_t)k * 256 + idx];
    __syncthreads();

    // Cholesky by warp 0 (lanes = rows)
    if (tid < 32) {
        const int i = tid;
        #pragma unroll 1
        for (int j = 0; j < DDIM; ++j) {
            float diag = 0.f;
            if (i == j) { diag = sqrtf(A[j][j]); A[j][j] = diag; }
            diag = __shfl_sync(0xffffffffu, diag, j);
            if (i > j && i < DDIM) A[i][j] = A[i][j] / diag;
            __syncwarp();
            if (i > j && i < DDIM) {
                const float lij = A[i][j];
                for (int t = j + 1; t <= i; ++t) A[i][t] -= lij * A[t][j];
            }
            __syncwarp();
        }
    }
    __syncthreads();

    // G[m][e] = sum_{t<=e} points[k][m][t] * L[e][t] + mu[k][e]
    for (int idx = tid; idx < MPTS * DDIM; idx += blockDim.x) {
        const int mrow = idx >> 4, e = idx & 15;
        const float* pr = points + ((size_t)k * MPTS + mrow) * DDIM;
        float acc = mu[k * DDIM + e];
        for (int t = 0; t <= e; ++t) acc = fmaf(pr[t], A[e][t], acc);
        Gs[mrow][e] = acc;
    }
    __syncthreads();

    // write transposed-packed Gt4 + cmeta
    for (int idx = tid; idx < MPTS * 4; idx += blockDim.x) {
        const int mrow = idx >> 2, e4 = idx & 3;
        const int col = k * MPTS + mrow;
        d_Gt4[e4 * NCOLS + col] = make_float4(Gs[mrow][4 * e4 + 0], Gs[mrow][4 * e4 + 1],
                                              Gs[mrow][4 * e4 + 2], Gs[mrow][4 * e4 + 3]);
    }

    const float lp2 = log2f(prop[k]);
    for (int mrow = tid; mrow < MPTS; mrow += blockDim.x) {
        float s = 0.f;
        #pragma unroll
        for (int e = 0; e < DDIM; ++e) { const float v = Gs[mrow][e]; s = fmaf(v, v, s); }
        d_cmeta[k * MPTS + mrow] = make_float2(s, lp2);
    }
}

// ---------------- Kernel 2: logits + softmax + outputs ----------------
// Sweep 1: each of 8 warps handles ALL 4 rows x its 1/8 column stripe (800 cols).
//          G column loads coalesced (transposed layout), amortized over 4 rows.
// Sweep 2/3: warp-pair-per-row mapping, float2-vectorized, logits resident in smem.
__global__ __launch_bounds__(TPB, 2)
void gml_main_kernel(const float* __restrict__ z, float* __restrict__ out) {
    extern __shared__ float sm[];
    float* slog  = sm;                    // [RPB][NCOLS]
    float* scomp = sm + SLOG_F;           // [RPB][NCOMP][2]
    float* sredA = scomp + SCOMP_F;       // [RPB][NSTRIPE]
    float* sredB = sredA + SREDA_F;       // [RPB][2]

    const int tid  = threadIdx.x;
    const int lane = tid & 31;
    const int w    = tid >> 5;

    // ---- Sweep-1 mapping: warp w = column stripe w, all 4 rows ----
    const int jbase = w * COLS_PER_STRIPE;
    const int row0  = blockIdx.x * RPB;

    // load z for 4 rows -> packed f32x2 regs + z2
    unsigned long long zp[4][8];
    float z2[4];
    #pragma unroll
    for (int r = 0; r < 4; ++r) {
        const float4* zf = reinterpret_cast<const float4*>(z + (size_t)(row0 + r) * DDIM);
        const float4 a0 = __ldg(zf + 0), a1 = __ldg(zf + 1);
        const float4 a2 = __ldg(zf + 2), a3 = __ldg(zf + 3);
        float s = a0.x * a0.x;
        s = fmaf(a0.y, a0.y, s); s = fmaf(a0.z, a0.z, s); s = fmaf(a0.w, a0.w, s);
        s = fmaf(a1.x, a1.x, s); s = fmaf(a1.y, a1.y, s); s = fmaf(a1.z, a1.z, s); s = fmaf(a1.w, a1.w, s);
        s = fmaf(a2.x, a2.x, s); s = fmaf(a2.y, a2.y, s); s = fmaf(a2.z, a2.z, s); s = fmaf(a2.w, a2.w, s);
        s = fmaf(a3.x, a3.x, s); s = fmaf(a3.y, a3.y, s); s = fmaf(a3.z, a3.z, s); s = fmaf(a3.w, a3.w, s);
        z2[r] = s;
        zp[r][0] = f2u2(a0.x, a0.y); zp[r][1] = f2u2(a0.z, a0.w);
        zp[r][2] = f2u2(a1.x, a1.y); zp[r][3] = f2u2(a1.z, a1.w);
        zp[r][4] = f2u2(a2.x, a2.y); zp[r][5] = f2u2(a2.z, a2.w);
        zp[r][6] = f2u2(a3.x, a3.y); zp[r][7] = f2u2(a3.z, a3.w);
    }

    const ulonglong2* gt = reinterpret_cast<const ulonglong2*>(d_Gt4);

    // ---- Sweep 1: logits (log2 domain), running max per row ----
    float mrun[4] = {-3.0e38f, -3.0e38f, -3.0e38f, -3.0e38f};
    #pragma unroll 1
    for (int it = 0; it < ITERS_S1; ++it) {
        const int j = jbase + it * 32 + lane;
        const ulonglong2 ga = __ldg(gt + 0 * NCOLS + j);
        const ulonglong2 gb = __ldg(gt + 1 * NCOLS + j);
        const ulonglong2 gc = __ldg(gt + 2 * NCOLS + j);
        const ulonglong2 gd = __ldg(gt + 3 * NCOLS + j);
        const float2 cm = __ldg(&d_cmeta[j]);
        #pragma unroll
        for (int r = 0; r < 4; ++r) {
            unsigned long long acc0 = 0ull, acc1 = 0ull;
            ffma2(acc0, ga.x, zp[r][0]); ffma2(acc1, ga.y, zp[r][1]);
            ffma2(acc0, gb.x, zp[r][2]); ffma2(acc1, gb.y, zp[r][3]);
            ffma2(acc0, gc.x, zp[r][4]); ffma2(acc1, gc.y, zp[r][5]);
            ffma2(acc0, gd.x, zp[r][6]); ffma2(acc1, gd.y, zp[r][7]);
            const float2 s0 = u2f2(acc0), s1 = u2f2(acc1);
            const float dot = (s0.x + s0.y) + (s1.x + s1.y);
            float d2 = fmaf(dot, -2.f, z2[r] + cm.x);
            d2 = fmaxf(d2, 0.f);
            const float l2v = fmaf(sqrtaf(d2), NEG_INV_SIGMA_LOG2E, cm.y);
            slog[r * NCOLS + j] = l2v;
            mrun[r] = fmaxf(mrun[r], l2v);
        }
    }
    #pragma unroll
    for (int r = 0; r < 4; ++r) {
        float m = mrun[r];
        #pragma unroll
        for (int o = 16; o; o >>= 1) m = fmaxf(m, __shfl_xor_sync(0xffffffffu, m, o));
        if (lane == 0) sredA[r * NSTRIPE + w] = m;
    }
    __syncthreads();

    // ---- Sweep-2/3 mapping: warp pair per row ----
    const int r    = w >> 1;              // row within block (0..3)
    const int h    = w & 1;               // which warp of the pair
    const int row  = blockIdx.x * RPB + r;
    float* srow = slog + r * NCOLS;

    float M2 = sredA[r * NSTRIPE];
    #pragma unroll
    for (int s = 1; s < NSTRIPE; ++s) M2 = fmaxf(M2, sredA[r * NSTRIPE + s]);

    // ---- Sweep 2: exp2 in place (float2), accumulate S ----
    float2* srow2 = reinterpret_cast<float2*>(srow);
    float srun = 0.f;
    #pragma unroll 2
    for (int it = 0; it < 50; ++it) {
        const int j2 = it * 64 + h * 32 + lane;     // float2 index, warp reads 64 consecutive floats
        float2 v = srow2[j2];
        v.x = ex2f(v.x - M2);
        v.y = ex2f(v.y - M2);
        srow2[j2] = v;
        srun += v.x + v.y;
    }
    #pragma unroll
    for (int o = 16; o; o >>= 1) srun += __shfl_xor_sync(0xffffffffu, srun, o);
    if (lane == 0) sredB[r * 2 + h] = srun;
    __syncthreads();
    const float invS = 1.0f / (sredB[r * 2] + sredB[r * 2 + 1]);

    // ---- Sweep 3: normalize (float2), write point_resp, per-component sums ----
    float* outp = out + (size_t)row * NCOLS;
    #pragma unroll 1
    for (int k = 0; k < NCOMP; ++k) {
        const int base = k * MPTS + h * 50;          // even element offset -> float2 aligned
        const float2* s2 = reinterpret_cast<const float2*>(srow + base);
        float2* o2 = reinterpret_cast<float2*>(outp + base);
        float ck = 0.f;
        if (lane < 25) {
            float2 v = s2[lane];
            v.x *= invS; v.y *= invS;
            o2[lane] = v;
            ck = v.x + v.y;
        }
        #pragma unroll
        for (int o = 16; o; o >>= 1) ck += __shfl_xor_sync(0xffffffffu, ck, o);
        if (lane == 0) scomp[(r * NCOMP + k) * 2 + h] = ck;
    }
    __syncthreads();

    // write comp_resp: 256 values per block, one per thread
    {
        const int rr = tid >> 6, kk = tid & 63;
        const int orow = blockIdx.x * RPB + rr;
        out[NPM + (size_t)orow * NCOMP + kk] = scomp[tid * 2] + scomp[tid * 2 + 1];
    }
}

// ---------------- launch ----------------
extern "C" void kernel_launch(void* const* d_in, const int* in_sizes, int n_in,
                              void* d_out, int out_size) {
    const float* z      = (const float*)d_in[0];
    const float* points = (const float*)d_in[1];
    const float* mu     = (const float*)d_in[2];
    const float* cov    = (const float*)d_in[3];
    const float* prop   = (const float*)d_in[4];
    float* out = (float*)d_out;

    cudaFuncSetAttribute(gml_main_kernel, cudaFuncAttributeMaxDynamicSharedMemorySize,
                         SMEM_BYTES);

    gml_prep_kernel<<<NCOMP, 128>>>(points, mu, cov, prop);
    gml_main_kernel<<<NBLK, TPB, SMEM_BYTES>>>(z, out);
}